// round 12
// baseline (speedup 1.0000x reference)
#include <cuda_runtime.h>
#include <cuda_bf16.h>
#include <cstdint>

#define DIM        4096
#define B          8
#define UP_OUT     1024               // N_KV * HEAD_DIM
#define KSPLIT     8                  // K-chunks for up-projection
#define TOKB       16                 // tokens per broadcast block

// Scratch (allocation-free rule: __device__ globals).
// g_x is zero-initialized at load; up accumulates into it atomically; the
// broadcast kernel re-zeros it every call, so every kernel_launch invocation
// sees g_x == 0 on entry (deterministic across graph replays).
__device__ float g_x[B * UP_OUT];     // up result   [8,1024]
__device__ float g_y[B * DIM];        // down result [8,4096]

// ---------------------------------------------------------------------------
// Kernel 1: up GEMV, K-split x8. 8192 warps / 1024 blocks; warp -> (col j,
// chunk s). Each warp streams 2 KB of W_up with the 4-iteration K loop fully
// unrolled (36 loads in flight). Lane 0 atomically accumulates the partial
// into g_x (8192 distinct addresses -> negligible REDG cost).
// ---------------------------------------------------------------------------
__global__ __launch_bounds__(256) void up_gemv(const float* __restrict__ emb,
                                               const float* __restrict__ Wup) {
    int gw   = (blockIdx.x * 256 + threadIdx.x) >> 5;  // 0..8191
    int lane = threadIdx.x & 31;
    int j = gw >> 3;                                   // output column 0..1023
    int s = gw & 7;                                    // K chunk 0..7

    const int C4 = DIM / 4 / KSPLIT;                   // 128 float4
    const float4* wrow = (const float4*)(Wup + (size_t)j * DIM) + s * C4;
    const float4* e4   = (const float4*)emb + s * C4;

    float acc[B];
#pragma unroll
    for (int b = 0; b < B; b++) acc[b] = 0.f;

#pragma unroll
    for (int k = 0; k < C4 / 32; k++) {                // 4 iters, fully unrolled
        int c = k * 32 + lane;
        float4 w = __ldg(&wrow[c]);
#pragma unroll
        for (int b = 0; b < B; b++) {
            float4 e = __ldg(&e4[b * (DIM / 4) + c]);
            acc[b] += e.x * w.x + e.y * w.y + e.z * w.z + e.w * w.w;
        }
    }
#pragma unroll
    for (int b = 0; b < B; b++) {
#pragma unroll
        for (int off = 16; off > 0; off >>= 1)
            acc[b] += __shfl_down_sync(0xffffffffu, acc[b], off);
    }
    if (lane == 0) {
#pragma unroll
        for (int b = 0; b < B; b++)
            atomicAdd(&g_x[b * UP_OUT + j], acc[b]);
    }
}

// ---------------------------------------------------------------------------
// Kernel 2: down GEMV, 512 blocks / 4096 warps (R4 lesson: never shrink).
// Staging now reads only the 32 KB g_x (no partial arrays).
// y[b,o] = sum_i val[b,i]*W_down[o,i], val[b,i] = x[b, ((i>>9)<<7)|(i&127)].
// ---------------------------------------------------------------------------
__global__ __launch_bounds__(256) void down_gemv(const float* __restrict__ Wdown) {
    __shared__ float sx[B * UP_OUT];                   // 32 KB
    {
        float4* dst = (float4*)sx;
        const float4* src = (const float4*)g_x;
        for (int i = threadIdx.x; i < B * UP_OUT / 4; i += 256)
            dst[i] = __ldg(src + i);
    }
    __syncthreads();

    int warp = (blockIdx.x * 256 + threadIdx.x) >> 5;  // 0..4095
    int lane = threadIdx.x & 31;

    const float4* wrow = (const float4*)(Wdown + (size_t)warp * DIM);
    float acc[B];
#pragma unroll
    for (int b = 0; b < B; b++) acc[b] = 0.f;

#pragma unroll 8
    for (int c = lane; c < DIM / 4; c += 32) {
        float4 w = __ldg(&wrow[c]);
        int i  = c * 4;
        int xi = ((i >> 9) << 7) | (i & 127);          // head -> kv head
#pragma unroll
        for (int b = 0; b < B; b++) {
            float4 v = *(const float4*)(sx + b * UP_OUT + xi);
            acc[b] += v.x * w.x + v.y * w.y + v.z * w.z + v.w * w.w;
        }
    }
#pragma unroll
    for (int b = 0; b < B; b++) {
#pragma unroll
        for (int off = 16; off > 0; off >>= 1)
            acc[b] += __shfl_down_sync(0xffffffffu, acc[b], off);
    }
    if (lane == 0) {
#pragma unroll
        for (int b = 0; b < B; b++) g_y[b * DIM + warp] = acc[b];
    }
}

// ---------------------------------------------------------------------------
// Kernel 3: broadcast via TMA bulk stores. 16 tokens per block (grid 1024).
// Each block stages the <=2 distinct y-rows its tokens need (seqlen >= 1024
// => at most one batch boundary per 16-token span) into smem, then issues one
// 16 KB cp.async.bulk store per token. Removes the scalar-STG/L1 wavefront
// bottleneck (R1: L1 62.9% ~ DRAM 61.8%). Block 0 also re-zeros g_x.
// ---------------------------------------------------------------------------
__global__ __launch_bounds__(256) void bcast_tma(float* __restrict__ out,
                                                 const void* __restrict__ seqlen_raw,
                                                 int total_tokens) {
    __shared__ alignas(128) float srow[2][DIM];        // 32 KB
    __shared__ int tb[TOKB];

    // Re-zero g_x for the next invocation (runs after down consumed it).
    if (blockIdx.x == 0) {
        for (int i = threadIdx.x; i < B * UP_OUT; i += 256) g_x[i] = 0.f;
    }

    int t0 = blockIdx.x * TOKB;

    // Per-token batch index (handles int32 OR int64 seqlen).
    if (threadIdx.x < TOKB) {
        const int*       s32 = (const int*)seqlen_raw;
        const long long* s64 = (const long long*)seqlen_raw;
        long long sum64 = 0;
#pragma unroll
        for (int i = 0; i < B; i++) sum64 += s64[i];
        bool use64 = (sum64 == (long long)total_tokens);
        int t = t0 + threadIdx.x;
        if (t >= total_tokens) t = total_tokens - 1;
        int acc = 0, b = 0;
#pragma unroll
        for (int i = 0; i < B; i++) {
            int len = use64 ? (int)s64[i] : s32[i];
            if (t >= acc + len) b = i + 1;
            acc += len;
        }
        tb[threadIdx.x] = (b < B) ? b : (B - 1);
    }
    __syncthreads();

    int b0 = tb[0];
    int b1 = tb[TOKB - 1];                             // batch monotonic in t

    // Stage the two (possibly identical) y rows.
    {
        const float4* y0 = (const float4*)(g_y + (size_t)b0 * DIM);
        const float4* y1 = (const float4*)(g_y + (size_t)b1 * DIM);
        float4* d0 = (float4*)srow[0];
        float4* d1 = (float4*)srow[1];
        for (int i = threadIdx.x; i < DIM / 4; i += 256) {
            d0[i] = __ldg(y0 + i);
            d1[i] = __ldg(y1 + i);
        }
    }
    __syncthreads();
    asm volatile("fence.proxy.async.shared::cta;" ::: "memory");

    if (threadIdx.x == 0) {
        uint32_t s0 = (uint32_t)__cvta_generic_to_shared(&srow[0][0]);
        uint32_t s1 = (uint32_t)__cvta_generic_to_shared(&srow[1][0]);
#pragma unroll
        for (int k = 0; k < TOKB; k++) {
            int t = t0 + k;
            if (t < total_tokens) {
                uint32_t src = (tb[k] == b0) ? s0 : s1;
                float* dst = out + (size_t)t * DIM;
                asm volatile(
                    "cp.async.bulk.global.shared::cta.bulk_group [%0], [%1], %2;"
                    :: "l"(dst), "r"(src), "r"((uint32_t)(DIM * sizeof(float)))
                    : "memory");
            }
        }
        asm volatile("cp.async.bulk.commit_group;" ::: "memory");
        asm volatile("cp.async.bulk.wait_group 0;" ::: "memory");
    }
    __syncthreads();   // smem must outlive the TMA reads
}

// ---------------------------------------------------------------------------
extern "C" void kernel_launch(void* const* d_in, const int* in_sizes, int n_in,
                              void* d_out, int out_size) {
    const float* emb   = (const float*)d_in[0];  // [8, 4096]
    const float* Wup   = (const float*)d_in[1];  // [1024, 4096]
    const float* Wdown = (const float*)d_in[2];  // [4096, 4096]
    const void*  seql  = d_in[3];                // [8] int32 or int64

    int total_tokens = out_size / DIM;           // 16384

    up_gemv<<<UP_OUT * KSPLIT / 8, 256>>>(emb, Wup);        // 1024 blocks
    down_gemv<<<DIM / 8, 256>>>(Wdown);                     // 512 blocks
    bcast_tma<<<(total_tokens + TOKB - 1) / TOKB, 256>>>((float*)d_out, seql, total_tokens);
}

// round 14
// speedup vs baseline: 1.0114x; 1.0114x over previous
#include <cuda_runtime.h>
#include <cuda_bf16.h>
#include <cstdint>

#define DIM        4096
#define B          8
#define UP_OUT     1024               // N_KV * HEAD_DIM
#define KSPLIT     4                  // K-chunks for up-projection

// Scratch (allocation-free rule: __device__ globals).
// g_x zero-init at load; up atomically accumulates; bcast block 0 re-zeros it
// after down consumed it, so every invocation sees g_x == 0 (deterministic).
__device__ float g_x[B * UP_OUT];     // up result   [8,1024]
__device__ float g_y[B * DIM];        // down result [8,4096]

// ---------------------------------------------------------------------------
// Kernel 1: up GEMV, K-split x4, 128-thread blocks (1024 blocks for SM
// spread). Warp -> (column j, chunk s); 8-iteration K loop fully unrolled
// (72 loads in flight). Lane 0 atomicAdds the partial into g_x.
// ---------------------------------------------------------------------------
__global__ __launch_bounds__(128) void up_gemv(const float* __restrict__ emb,
                                               const float* __restrict__ Wup) {
    int gw   = (blockIdx.x * 128 + threadIdx.x) >> 5;  // 0..4095
    int lane = threadIdx.x & 31;
    int j = gw >> 2;                                   // output column 0..1023
    int s = gw & 3;                                    // K chunk 0..3

    const int C4 = DIM / 4 / KSPLIT;                   // 256 float4
    const float4* wrow = (const float4*)(Wup + (size_t)j * DIM) + s * C4;
    const float4* e4   = (const float4*)emb + s * C4;

    float acc[B];
#pragma unroll
    for (int b = 0; b < B; b++) acc[b] = 0.f;

#pragma unroll
    for (int k = 0; k < C4 / 32; k++) {                // 8 iters, fully unrolled
        int c = k * 32 + lane;
        float4 w = __ldg(&wrow[c]);
#pragma unroll
        for (int b = 0; b < B; b++) {
            float4 e = __ldg(&e4[b * (DIM / 4) + c]);
            acc[b] += e.x * w.x + e.y * w.y + e.z * w.z + e.w * w.w;
        }
    }
#pragma unroll
    for (int b = 0; b < B; b++) {
#pragma unroll
        for (int off = 16; off > 0; off >>= 1)
            acc[b] += __shfl_down_sync(0xffffffffu, acc[b], off);
    }
    if (lane == 0) {
#pragma unroll
        for (int b = 0; b < B; b++)
            atomicAdd(&g_x[b * UP_OUT + j], acc[b]);
    }
}

// ---------------------------------------------------------------------------
// Kernel 2: down GEMV, 512 blocks / 4096 warps (R4: never shrink the grid).
// Stages the 32 KB g_x in smem; warp per output column, unroll-8 W stream.
// y[b,o] = sum_i val[b,i]*W_down[o,i], val[b,i] = x[b, ((i>>9)<<7)|(i&127)].
// ---------------------------------------------------------------------------
__global__ __launch_bounds__(256) void down_gemv(const float* __restrict__ Wdown) {
    __shared__ float sx[B * UP_OUT];                   // 32 KB
    {
        float4* dst = (float4*)sx;
        const float4* src = (const float4*)g_x;
        for (int i = threadIdx.x; i < B * UP_OUT / 4; i += 256)
            dst[i] = __ldg(src + i);
    }
    __syncthreads();

    int warp = (blockIdx.x * 256 + threadIdx.x) >> 5;  // 0..4095
    int lane = threadIdx.x & 31;

    const float4* wrow = (const float4*)(Wdown + (size_t)warp * DIM);
    float acc[B];
#pragma unroll
    for (int b = 0; b < B; b++) acc[b] = 0.f;

#pragma unroll 8
    for (int c = lane; c < DIM / 4; c += 32) {
        float4 w = __ldg(&wrow[c]);
        int i  = c * 4;
        int xi = ((i >> 9) << 7) | (i & 127);          // head -> kv head
#pragma unroll
        for (int b = 0; b < B; b++) {
            float4 v = *(const float4*)(sx + b * UP_OUT + xi);
            acc[b] += v.x * w.x + v.y * w.y + v.z * w.z + v.w * w.w;
        }
    }
#pragma unroll
    for (int b = 0; b < B; b++) {
#pragma unroll
        for (int off = 16; off > 0; off >>= 1)
            acc[b] += __shfl_down_sync(0xffffffffu, acc[b], off);
    }
    if (lane == 0) {
#pragma unroll
        for (int b = 0; b < B; b++) g_y[b * DIM + warp] = acc[b];
    }
}

// ---------------------------------------------------------------------------
// Kernel 3: broadcast, one block per token (grid 16384 — proven shape), but
// with 256-bit streaming stores (st.global.cs.v8.b32) to halve the STG /
// L1-wavefront count that co-limited the scalar version (R1: L1 62.9% ~
// DRAM 61.8%). Each thread writes 2 x 32 B per row. Block 0 re-zeros g_x.
// ---------------------------------------------------------------------------
__global__ __launch_bounds__(256) void broadcast_rows(float* __restrict__ out,
                                                      const void* __restrict__ seqlen_raw,
                                                      int total_tokens) {
    __shared__ int sb;
    if (blockIdx.x == 0) {   // re-zero g_x for the next invocation
        for (int i = threadIdx.x; i < B * UP_OUT; i += 256) g_x[i] = 0.f;
    }
    if (threadIdx.x == 0) {
        const int*       s32 = (const int*)seqlen_raw;
        const long long* s64 = (const long long*)seqlen_raw;
        long long sum64 = 0;
#pragma unroll
        for (int i = 0; i < B; i++) sum64 += s64[i];
        bool use64 = (sum64 == (long long)total_tokens);
        int t = blockIdx.x;
        int acc = 0, b = 0;
#pragma unroll
        for (int i = 0; i < B; i++) {
            int len = use64 ? (int)s64[i] : s32[i];
            if (t >= acc + len) b = i + 1;
            acc += len;
        }
        sb = (b < B) ? b : (B - 1);
    }
    __syncthreads();

    const float4* yrow = (const float4*)(g_y + (size_t)sb * DIM);
    float*        orow = out + (size_t)blockIdx.x * DIM;

#pragma unroll
    for (int k = 0; k < 2; k++) {
        int v = k * 256 + threadIdx.x;          // 32B-unit index, 0..511
        float4 a = __ldg(yrow + 2 * v);
        float4 c = __ldg(yrow + 2 * v + 1);
        asm volatile(
            "st.global.cs.v8.b32 [%0], {%1,%2,%3,%4,%5,%6,%7,%8};"
            :: "l"(orow + 8 * v),
               "r"(__float_as_uint(a.x)), "r"(__float_as_uint(a.y)),
               "r"(__float_as_uint(a.z)), "r"(__float_as_uint(a.w)),
               "r"(__float_as_uint(c.x)), "r"(__float_as_uint(c.y)),
               "r"(__float_as_uint(c.z)), "r"(__float_as_uint(c.w))
            : "memory");
    }
}

// ---------------------------------------------------------------------------
extern "C" void kernel_launch(void* const* d_in, const int* in_sizes, int n_in,
                              void* d_out, int out_size) {
    const float* emb   = (const float*)d_in[0];  // [8, 4096]
    const float* Wup   = (const float*)d_in[1];  // [1024, 4096]
    const float* Wdown = (const float*)d_in[2];  // [4096, 4096]
    const void*  seql  = d_in[3];                // [8] int32 or int64

    int total_tokens = out_size / DIM;           // 16384

    up_gemv<<<UP_OUT * KSPLIT / 4, 128>>>(emb, Wup);   // 1024 blocks, 4096 warps
    down_gemv<<<DIM / 8, 256>>>(Wdown);                // 512 blocks, 4096 warps
    broadcast_rows<<<total_tokens, 256>>>((float*)d_out, seql, total_tokens);
}